// round 15
// baseline (speedup 1.0000x reference)
#include <cuda_runtime.h>
#include <cuda_fp16.h>
#include <cstdint>

// ---------------------------------------------------------------------------
//   x [32,256,32,32] f32, weight [256,256,3,3] f32, gamma/beta [1024] f32
//   out [32,256,32,32] f32
//
// Single-pass fp16 m16n8k16 mma.sync binary-weight conv + EXACT BN mean.
//   S = sum(+-x); A = fp16(x) (err sigma ~0.008 S-units), B = +-1, fp32 acc.
//   Channel mean computed EXACTLY via weight-independent windowed sums:
//     mean_c = (1/32768) * sum_{ci,tap} sign(w) * U[ci][tap],
//     U[ci][tap] = sum_{b,h,w} x[b,ci,h+dh-1,w+dw-1]   (double-reduced).
//   Variance from noisy S (error ~1e-7 relative; margin sign is scale-
//   invariant here). Near-threshold decisions (|margin| < sc*TAU) flagged
//   in k_out, recomputed exactly (double) in k_fix against the exact mean.
// ---------------------------------------------------------------------------

#define TAU   0.08f
#define CAP   4194304

static __device__ uint32_t g_wB[4 * 9 * 32 * 256];    // [g][tap][kpair][co] f16x2 (+-1)
static __device__ float    g_alpha[256];
static __device__ float    g_psum[33554432];          // [b][g*256+co][h][w]  (holds S)
static __device__ double   g_U[256 * 9];              // windowed x sums [ci][tap]
static __device__ float    g_scale[1024];
static __device__ float    g_bias[1024];
static __device__ int      g_cnt;
static __device__ int      g_list[CAP];

// ---------------------------------------------------------------------------
// K0: alpha[co] = mean |w|, fp16 +-1 weight pack, zero the flag counter.
// ---------------------------------------------------------------------------
__global__ void k_prep(const float* __restrict__ w) {
    const int co = blockIdx.x;
    const int t  = threadIdx.x;          // 256 threads
    if (co == 0 && t == 0) g_cnt = 0;
    __shared__ float red[256];
    const float* wc = w + co * 2304;
    float s = 0.0f;
    for (int i = t; i < 2304; i += 256) s += fabsf(wc[i]);
    red[t] = s;
    __syncthreads();
    for (int off = 128; off; off >>= 1) {
        if (t < off) red[t] += red[t + off];
        __syncthreads();
    }
    if (t == 0) g_alpha[co] = red[0] * (1.0f / 2304.0f);
    uint16_t* wb16 = reinterpret_cast<uint16_t*>(g_wB);
    for (int i = t; i < 2304; i += 256) {
        const int ci  = i / 9;
        const int tap = i - ci * 9;
        const int g   = ci >> 6;
        const int cig = ci & 63;
        const int kp  = cig >> 1;
        const int hlf = cig & 1;
        wb16[((((size_t)(g * 9 + tap) * 32 + kp) * 256) + co) * 2 + hlf] =
            (wc[i] >= 0.0f) ? 0x3C00u : 0xBC00u;   // fp16 +-1
    }
}

// ---------------------------------------------------------------------------
// K0b: U[ci][tap] = sum over (b,h,w) of padded-shifted x. One block per
// (ci,tap); fp32 per-thread partials, double tree reduction (deterministic).
// ---------------------------------------------------------------------------
__global__ void k_usum(const float* __restrict__ x) {
    const int ci  = blockIdx.x / 9;
    const int tap = blockIdx.x - ci * 9;
    const int dh  = tap / 3 - 1;
    const int dw  = tap % 3 - 1;
    const int t   = threadIdx.x;     // 256
    float part = 0.0f;
    for (int i = t; i < 32768; i += 256) {
        const int b = i >> 10;
        const int p = i & 1023;
        const int gr = (p >> 5) + dh;
        const int gc = (p & 31) + dw;
        if ((unsigned)gr < 32u && (unsigned)gc < 32u)
            part += x[((size_t)(b * 256 + ci)) * 1024 + gr * 32 + gc];
    }
    __shared__ double red[256];
    red[t] = (double)part;
    __syncthreads();
    for (int off = 128; off; off >>= 1) {
        if (t < off) red[t] += red[t + off];
        __syncthreads();
    }
    if (t == 0) g_U[ci * 9 + tap] = red[0];
}

// ---------------------------------------------------------------------------
// K1: fp16 m16n8k16 mma.sync conv, single pass.
// CTA = D[128 px][256 co] for (b,g,rowTile). 512 threads = 16 warps (4Mx4N);
// warp tile 32 px x 64 co.
// smem u32: B[0,8448)  XHI[8448,15360)
// ---------------------------------------------------------------------------
#define SM_B    0
#define SM_XHI  8448
#define SM_WORDS 15360
#define SM_BYTES (SM_WORDS * 4)

__device__ __forceinline__ void mma_f16(float& d0, float& d1, float& d2, float& d3,
                                        uint32_t a0, uint32_t a1, uint32_t a2, uint32_t a3,
                                        uint32_t b0, uint32_t b1) {
    asm volatile(
        "mma.sync.aligned.m16n8k16.row.col.f32.f16.f16.f32 "
        "{%0,%1,%2,%3}, {%4,%5,%6,%7}, {%8,%9}, {%0,%1,%2,%3};"
        : "+f"(d0), "+f"(d1), "+f"(d2), "+f"(d3)
        : "r"(a0), "r"(a1), "r"(a2), "r"(a3), "r"(b0), "r"(b1));
}

__global__ void __launch_bounds__(512, 1)
k_conv(const float* __restrict__ x) {
    extern __shared__ uint32_t smu[];
    const int tid  = threadIdx.x;
    const int wid  = tid >> 5;
    const int lane = tid & 31;
    const int lq   = lane >> 2;
    const int lr4  = lane & 3;
    const int warpM = wid >> 2;
    const int warpN = wid & 3;

    const int b  = blockIdx.z;
    const int g  = blockIdx.y;
    const int pt = blockIdx.x;
    const int r0 = pt * 4;

    // ---- stage x slab as fp16, ci pairs packed: [32 cipair][6][36] ----
    const float* xg = x + (size_t)(b * 256 + g * 64) * 1024;
    for (int i = tid; i < 6912; i += 512) {
        const int cp  = i / 216;
        const int rem = i - cp * 216;
        const int lrr = rem / 36;
        const int lc  = rem - lrr * 36;
        const int gr  = r0 - 1 + lrr;
        const int gc  = lc - 1;
        float v0 = 0.0f, v1 = 0.0f;
        if ((unsigned)gr < 32u && (unsigned)gc < 32u) {
            v0 = xg[(2 * cp) * 1024 + gr * 32 + gc];
            v1 = xg[(2 * cp + 1) * 1024 + gr * 32 + gc];
        }
        const __half h0 = __float2half_rn(v0);
        const __half h1 = __float2half_rn(v1);
        smu[SM_XHI + i] = (uint32_t)__half_as_ushort(h0) |
                          ((uint32_t)__half_as_ushort(h1) << 16);
    }

    float acc[2][8][4];
#pragma unroll
    for (int mt = 0; mt < 2; mt++)
#pragma unroll
        for (int n = 0; n < 8; n++)
#pragma unroll
            for (int k = 0; k < 4; k++) acc[mt][n][k] = 0.0f;

    const uint32_t* srcB = g_wB + (size_t)g * 9 * 8192;

    for (int tap = 0; tap < 9; ++tap) {
        __syncthreads();
        const uint32_t* src = srcB + (size_t)tap * 8192;
        for (int i = tid; i < 8192; i += 512) {
            smu[SM_B + (i >> 8) * 264 + (i & 255)] = src[i];
        }
        __syncthreads();

        const int kh = tap / 3;
        const int kw = tap - kh * 3;
        const int abase = (warpM + kh) * 36 + kw + lq;
        const uint32_t* bp0 = smu + SM_B + lr4 * 264 + warpN * 64 + lq;

#pragma unroll
        for (int kc = 0; kc < 4; ++kc) {
            uint32_t b0[8], b1[8];
            const uint32_t* bp = bp0 + kc * 8 * 264;
#pragma unroll
            for (int n = 0; n < 8; ++n) {
                b0[n] = bp[n * 8];
                b1[n] = bp[4 * 264 + n * 8];
            }
            const uint32_t* sxp = smu + SM_XHI + (kc * 8 + lr4) * 216 + abase;
            uint32_t A[2][4];
#pragma unroll
            for (int mt = 0; mt < 2; ++mt) {
                A[mt][0] = sxp[mt * 16];
                A[mt][1] = sxp[mt * 16 + 8];
                A[mt][2] = sxp[4 * 216 + mt * 16];
                A[mt][3] = sxp[4 * 216 + mt * 16 + 8];
            }
#pragma unroll
            for (int n = 0; n < 8; ++n)
#pragma unroll
                for (int mt = 0; mt < 2; ++mt)
                    mma_f16(acc[mt][n][0], acc[mt][n][1], acc[mt][n][2], acc[mt][n][3],
                            A[mt][0], A[mt][1], A[mt][2], A[mt][3],
                            b0[n], b1[n]);
        }
    }

    // ---- epilogue: D[px][co] -> g_psum[b][g*256+co][px] ----
    const int rimg = r0 + warpM;
#pragma unroll
    for (int mt = 0; mt < 2; ++mt) {
        const int px0 = rimg * 32 + mt * 16 + lq;
#pragma unroll
        for (int n = 0; n < 8; ++n) {
            const int co = g * 256 + warpN * 64 + n * 8 + lr4 * 2;
            float* base = g_psum + ((size_t)(b * 1024 + co)) * 1024;
            base[px0]            = acc[mt][n][0];
            base[1024 + px0]     = acc[mt][n][1];
            base[px0 + 8]        = acc[mt][n][2];
            base[1024 + px0 + 8] = acc[mt][n][3];
        }
    }
}

// ---------------------------------------------------------------------------
// K2: E[S^2] from noisy psum + EXACT mean from g_U and weight signs.
// ---------------------------------------------------------------------------
__global__ void k_stats(const float* __restrict__ gamma,
                        const float* __restrict__ beta,
                        const float* __restrict__ w) {
    const int ch = blockIdx.x;     // 1024
    const int t  = threadIdx.x;    // 256
    const int g  = ch >> 8;
    const int co = ch & 255;
    __shared__ float  rq[256];
    __shared__ double rm[64];

    float q = 0.0f;
    for (int i = t; i < 32768; i += 256) {
        const int bb = i >> 10;
        const int px = i & 1023;
        const float v = g_psum[((size_t)(bb * 1024 + ch)) * 1024 + px];
        q += v * v;
    }
    rq[t] = q;

    // exact mean: threads 0..63 each handle one cig (9 taps)
    if (t < 64) {
        const int ciglob = g * 64 + t;
        const float* wc = w + (size_t)co * 2304 + (size_t)ciglob * 9;
        double m = 0.0;
#pragma unroll
        for (int tap = 0; tap < 9; ++tap) {
            const double u = g_U[ciglob * 9 + tap];
            m += (wc[tap] >= 0.0f) ? u : -u;
        }
        rm[t] = m;
    }
    __syncthreads();
    for (int off = 128; off; off >>= 1) {
        if (t < off) rq[t] += rq[t + off];
        __syncthreads();
    }
    if (t == 0) {
        double msum = 0.0;
        for (int i = 0; i < 64; ++i) msum += rm[i];
        const double mean = msum * (1.0 / 32768.0);
        const double var  = (double)rq[0] * (1.0 / 32768.0) - mean * mean;
        const double a    = (double)g_alpha[co];
        const double inv  = (double)gamma[ch] / sqrt(a * a * var + 1e-5);
        const double sc   = a * inv;
        g_scale[ch] = (float)sc;
        g_bias[ch]  = (float)((double)beta[ch] - mean * sc);
    }
}

// ---------------------------------------------------------------------------
// K3: threshold + merge + qrelu LUT; flag near-threshold pixels.
// ---------------------------------------------------------------------------
__global__ void k_out(float* __restrict__ out) {
    const int idx = blockIdx.x * 256 + threadIdx.x;
    const int b    = idx >> 16;
    const int qb   = idx & 65535;
    const int co   = qb >> 8;
    const int pix4 = qb & 255;

    const float4* pb = reinterpret_cast<const float4*>(g_psum);
    int c0 = 0, c1 = 0, c2 = 0, c3 = 0;
    bool f0 = false, f1 = false, f2 = false, f3 = false;
#pragma unroll
    for (int g = 0; g < 4; g++) {
        const int chan = g * 256 + co;
        const float4 p = pb[(size_t)(b * 1024 + chan) * 256 + pix4];
        const float sc = g_scale[chan];
        const float bi = g_bias[chan];
        const float band = fabsf(sc) * TAU;
        const float m0 = p.x * sc + bi;
        const float m1 = p.y * sc + bi;
        const float m2 = p.z * sc + bi;
        const float m3 = p.w * sc + bi;
        c0 += (m0 >= 0.0f); f0 |= (fabsf(m0) < band);
        c1 += (m1 >= 0.0f); f1 |= (fabsf(m1) < band);
        c2 += (m2 >= 0.0f); f2 |= (fabsf(m2) < band);
        c3 += (m3 >= 0.0f); f3 |= (fabsf(m3) < band);
    }
    const float Q3 = (8.0f / 15.0f) * 4.0f;
    float4 o;
    o.x = (c0 == 4) ? 4.0f : ((c0 == 3) ? Q3 : 0.0f);
    o.y = (c1 == 4) ? 4.0f : ((c1 == 3) ? Q3 : 0.0f);
    o.z = (c2 == 4) ? 4.0f : ((c2 == 3) ? Q3 : 0.0f);
    o.w = (c3 == 4) ? 4.0f : ((c3 == 3) ? Q3 : 0.0f);
    reinterpret_cast<float4*>(out)[idx] = o;

    if (f0 | f1 | f2 | f3) {
        const int base = (b << 18) | (co << 10) | (pix4 << 2);
#pragma unroll
        for (int comp = 0; comp < 4; ++comp) {
            const bool f = (comp == 0) ? f0 : (comp == 1) ? f1 : (comp == 2) ? f2 : f3;
            if (f) {
                const int slot = atomicAdd(&g_cnt, 1);
                if (slot < CAP) g_list[slot] = base | comp;
            }
        }
    }
}

// ---------------------------------------------------------------------------
// K4: exact (double) recompute of flagged decisions; rewrite out. Idempotent.
// ---------------------------------------------------------------------------
__global__ void k_fix(const float* __restrict__ x, const float* __restrict__ w,
                      float* __restrict__ out) {
    const int n = (g_cnt < CAP) ? g_cnt : CAP;
    for (int i = blockIdx.x * blockDim.x + threadIdx.x; i < n;
         i += gridDim.x * blockDim.x) {
        const int item = g_list[i];
        const int b   = item >> 18;
        const int co  = (item >> 10) & 255;
        const int pix = item & 1023;
        const int h = pix >> 5, wp = pix & 31;
        int c = 0;
#pragma unroll 1
        for (int g = 0; g < 4; g++) {
            const int chan = g * 256 + co;
            const float sc = g_scale[chan];
            const float bi = g_bias[chan];
            const float S  = g_psum[((size_t)(b * 1024 + chan)) * 1024 + pix];
            const float m  = S * sc + bi;
            int bit;
            if (fabsf(m) < fabsf(sc) * TAU) {
                double s = 0.0;
                const float* xb = x + ((size_t)(b * 256 + g * 64)) * 1024;
                const float* wb = w + (size_t)co * 2304 + (size_t)g * 64 * 9;
                for (int cig = 0; cig < 64; cig++) {
                    const float* xc = xb + cig * 1024;
                    const float* wc = wb + cig * 9;
#pragma unroll
                    for (int kh = 0; kh < 3; kh++) {
                        const int hh = h + kh - 1;
                        if ((unsigned)hh >= 32u) continue;
#pragma unroll
                        for (int kw = 0; kw < 3; kw++) {
                            const int ww = wp + kw - 1;
                            if ((unsigned)ww >= 32u) continue;
                            const float xv = __ldg(xc + hh * 32 + ww);
                            s += (__ldg(wc + kh * 3 + kw) >= 0.0f) ? (double)xv
                                                                   : -(double)xv;
                        }
                    }
                }
                const double md = s * (double)sc + (double)bi;
                bit = (md >= 0.0);
            } else {
                bit = (m >= 0.0f);
            }
            c += bit;
        }
        const float Q3 = (8.0f / 15.0f) * 4.0f;
        out[((size_t)(b * 256 + co)) * 1024 + pix] =
            (c == 4) ? 4.0f : ((c == 3) ? Q3 : 0.0f);
    }
}

// ---------------------------------------------------------------------------
extern "C" void kernel_launch(void* const* d_in, const int* in_sizes, int n_in,
                              void* d_out, int out_size) {
    const float* x      = (const float*)d_in[0];
    const float* weight = (const float*)d_in[1];
    const float* gamma  = (const float*)d_in[2];
    const float* beta   = (const float*)d_in[3];
    float* out = (float*)d_out;

    cudaFuncSetAttribute(k_conv, cudaFuncAttributeMaxDynamicSharedMemorySize, SM_BYTES);

    k_prep<<<256, 256>>>(weight);
    k_usum<<<2304, 256>>>(x);
    k_conv<<<dim3(8, 4, 32), 512, SM_BYTES>>>(x);
    k_stats<<<1024, 256>>>(gamma, beta, weight);
    k_out<<<8192, 256>>>(out);
    k_fix<<<1024, 128>>>(x, weight, out);
}

// round 16
// speedup vs baseline: 2.5425x; 2.5425x over previous
#include <cuda_runtime.h>
#include <cuda_fp16.h>
#include <cstdint>

// ---------------------------------------------------------------------------
//   x [32,256,32,32] f32, weight [256,256,3,3] f32, gamma/beta [1024] f32
//   out [32,256,32,32] f32
//
// Single-pass fp16 m16n8k16 mma.sync binary-weight conv + EXACT BN mean +
// warp-cooperative exact rescue over an HWC transpose of x.
//   S = sum(+-x); A = fp16(x) (err sigma ~5e-3 S-units), B = +-1, fp32 acc.
//   mean_c exact via U[ci][tap] windowed sums (weight-independent).
//   |margin| < sc*TAU decisions flagged in k_out; k_fix recomputes them in
//   double from xt[b][h][w][ci] (coalesced over ci) + raw weights.
// ---------------------------------------------------------------------------

#define TAU   0.08f
#define CAP   4194304

static __device__ uint32_t g_wB[4 * 9 * 32 * 256];    // [g][tap][kpair][co] f16x2 (+-1)
static __device__ float    g_alpha[256];
static __device__ float    g_psum[33554432];          // [b][g*256+co][h][w]  (holds S)
static __device__ float    g_xt[8388608];             // [b][h][w][ci]  (HWC transpose)
static __device__ double   g_U[256 * 9];              // windowed x sums [ci][tap]
static __device__ float    g_scale[1024];
static __device__ float    g_bias[1024];
static __device__ int      g_cnt;
static __device__ int      g_list[CAP];

// ---------------------------------------------------------------------------
// K0: alpha[co] = mean |w|, fp16 +-1 weight pack, zero the flag counter.
// ---------------------------------------------------------------------------
__global__ void k_prep(const float* __restrict__ w) {
    const int co = blockIdx.x;
    const int t  = threadIdx.x;          // 256 threads
    if (co == 0 && t == 0) g_cnt = 0;
    __shared__ float red[256];
    const float* wc = w + co * 2304;
    float s = 0.0f;
    for (int i = t; i < 2304; i += 256) s += fabsf(wc[i]);
    red[t] = s;
    __syncthreads();
    for (int off = 128; off; off >>= 1) {
        if (t < off) red[t] += red[t + off];
        __syncthreads();
    }
    if (t == 0) g_alpha[co] = red[0] * (1.0f / 2304.0f);
    uint16_t* wb16 = reinterpret_cast<uint16_t*>(g_wB);
    for (int i = t; i < 2304; i += 256) {
        const int ci  = i / 9;
        const int tap = i - ci * 9;
        const int g   = ci >> 6;
        const int cig = ci & 63;
        const int kp  = cig >> 1;
        const int hlf = cig & 1;
        wb16[((((size_t)(g * 9 + tap) * 32 + kp) * 256) + co) * 2 + hlf] =
            (wc[i] >= 0.0f) ? 0x3C00u : 0xBC00u;   // fp16 +-1
    }
}

// ---------------------------------------------------------------------------
// K0b: U[ci][tap] = sum over (b,h,w) of padded-shifted x (double-reduced).
// ---------------------------------------------------------------------------
__global__ void k_usum(const float* __restrict__ x) {
    const int ci  = blockIdx.x / 9;
    const int tap = blockIdx.x - ci * 9;
    const int dh  = tap / 3 - 1;
    const int dw  = tap % 3 - 1;
    const int t   = threadIdx.x;     // 256
    float part = 0.0f;
    for (int i = t; i < 32768; i += 256) {
        const int b = i >> 10;
        const int p = i & 1023;
        const int gr = (p >> 5) + dh;
        const int gc = (p & 31) + dw;
        if ((unsigned)gr < 32u && (unsigned)gc < 32u)
            part += x[((size_t)(b * 256 + ci)) * 1024 + gr * 32 + gc];
    }
    __shared__ double red[256];
    red[t] = (double)part;
    __syncthreads();
    for (int off = 128; off; off >>= 1) {
        if (t < off) red[t] += red[t + off];
        __syncthreads();
    }
    if (t == 0) g_U[ci * 9 + tap] = red[0];
}

// ---------------------------------------------------------------------------
// K0c: transpose x [b][ci][px] -> xt [b][px][ci]  (32x32 smem tiles).
// grid (8 ciTiles, 32 pxTiles, 32 b), block (32, 8).
// ---------------------------------------------------------------------------
__global__ void k_xt(const float* __restrict__ x) {
    __shared__ float t[32][33];
    const int b  = blockIdx.z;
    const int pt = blockIdx.y;       // px / 32
    const int ct = blockIdx.x;       // ci / 32
    const int tx = threadIdx.x;      // 0..31
    const int ty = threadIdx.y;      // 0..7
#pragma unroll
    for (int j = 0; j < 4; ++j) {
        const int ci = ct * 32 + ty + 8 * j;
        t[ty + 8 * j][tx] = x[((size_t)(b * 256 + ci)) * 1024 + pt * 32 + tx];
    }
    __syncthreads();
#pragma unroll
    for (int j = 0; j < 4; ++j) {
        const int px = pt * 32 + ty + 8 * j;
        g_xt[((size_t)(b * 1024 + px)) * 256 + ct * 32 + tx] = t[tx][ty + 8 * j];
    }
}

// ---------------------------------------------------------------------------
// K1: fp16 m16n8k16 mma.sync conv, single pass.
// CTA = D[128 px][256 co] for (b,g,rowTile). 512 threads = 16 warps (4Mx4N);
// warp tile 32 px x 64 co.
// ---------------------------------------------------------------------------
#define SM_B    0
#define SM_XHI  8448
#define SM_WORDS 15360
#define SM_BYTES (SM_WORDS * 4)

__device__ __forceinline__ void mma_f16(float& d0, float& d1, float& d2, float& d3,
                                        uint32_t a0, uint32_t a1, uint32_t a2, uint32_t a3,
                                        uint32_t b0, uint32_t b1) {
    asm volatile(
        "mma.sync.aligned.m16n8k16.row.col.f32.f16.f16.f32 "
        "{%0,%1,%2,%3}, {%4,%5,%6,%7}, {%8,%9}, {%0,%1,%2,%3};"
        : "+f"(d0), "+f"(d1), "+f"(d2), "+f"(d3)
        : "r"(a0), "r"(a1), "r"(a2), "r"(a3), "r"(b0), "r"(b1));
}

__global__ void __launch_bounds__(512, 1)
k_conv(const float* __restrict__ x) {
    extern __shared__ uint32_t smu[];
    const int tid  = threadIdx.x;
    const int wid  = tid >> 5;
    const int lane = tid & 31;
    const int lq   = lane >> 2;
    const int lr4  = lane & 3;
    const int warpM = wid >> 2;
    const int warpN = wid & 3;

    const int b  = blockIdx.z;
    const int g  = blockIdx.y;
    const int pt = blockIdx.x;
    const int r0 = pt * 4;

    // ---- stage x slab as fp16, ci pairs packed: [32 cipair][6][36] ----
    const float* xg = x + (size_t)(b * 256 + g * 64) * 1024;
    for (int i = tid; i < 6912; i += 512) {
        const int cp  = i / 216;
        const int rem = i - cp * 216;
        const int lrr = rem / 36;
        const int lc  = rem - lrr * 36;
        const int gr  = r0 - 1 + lrr;
        const int gc  = lc - 1;
        float v0 = 0.0f, v1 = 0.0f;
        if ((unsigned)gr < 32u && (unsigned)gc < 32u) {
            v0 = xg[(2 * cp) * 1024 + gr * 32 + gc];
            v1 = xg[(2 * cp + 1) * 1024 + gr * 32 + gc];
        }
        const __half h0 = __float2half_rn(v0);
        const __half h1 = __float2half_rn(v1);
        smu[SM_XHI + i] = (uint32_t)__half_as_ushort(h0) |
                          ((uint32_t)__half_as_ushort(h1) << 16);
    }

    float acc[2][8][4];
#pragma unroll
    for (int mt = 0; mt < 2; mt++)
#pragma unroll
        for (int n = 0; n < 8; n++)
#pragma unroll
            for (int k = 0; k < 4; k++) acc[mt][n][k] = 0.0f;

    const uint32_t* srcB = g_wB + (size_t)g * 9 * 8192;

    for (int tap = 0; tap < 9; ++tap) {
        __syncthreads();
        const uint32_t* src = srcB + (size_t)tap * 8192;
        for (int i = tid; i < 8192; i += 512) {
            smu[SM_B + (i >> 8) * 264 + (i & 255)] = src[i];
        }
        __syncthreads();

        const int kh = tap / 3;
        const int kw = tap - kh * 3;
        const int abase = (warpM + kh) * 36 + kw + lq;
        const uint32_t* bp0 = smu + SM_B + lr4 * 264 + warpN * 64 + lq;

#pragma unroll
        for (int kc = 0; kc < 4; ++kc) {
            uint32_t b0[8], b1[8];
            const uint32_t* bp = bp0 + kc * 8 * 264;
#pragma unroll
            for (int n = 0; n < 8; ++n) {
                b0[n] = bp[n * 8];
                b1[n] = bp[4 * 264 + n * 8];
            }
            const uint32_t* sxp = smu + SM_XHI + (kc * 8 + lr4) * 216 + abase;
            uint32_t A[2][4];
#pragma unroll
            for (int mt = 0; mt < 2; ++mt) {
                A[mt][0] = sxp[mt * 16];
                A[mt][1] = sxp[mt * 16 + 8];
                A[mt][2] = sxp[4 * 216 + mt * 16];
                A[mt][3] = sxp[4 * 216 + mt * 16 + 8];
            }
#pragma unroll
            for (int n = 0; n < 8; ++n)
#pragma unroll
                for (int mt = 0; mt < 2; ++mt)
                    mma_f16(acc[mt][n][0], acc[mt][n][1], acc[mt][n][2], acc[mt][n][3],
                            A[mt][0], A[mt][1], A[mt][2], A[mt][3],
                            b0[n], b1[n]);
        }
    }

    // ---- epilogue: D[px][co] -> g_psum[b][g*256+co][px] ----
    const int rimg = r0 + warpM;
#pragma unroll
    for (int mt = 0; mt < 2; ++mt) {
        const int px0 = rimg * 32 + mt * 16 + lq;
#pragma unroll
        for (int n = 0; n < 8; ++n) {
            const int co = g * 256 + warpN * 64 + n * 8 + lr4 * 2;
            float* base = g_psum + ((size_t)(b * 1024 + co)) * 1024;
            base[px0]            = acc[mt][n][0];
            base[1024 + px0]     = acc[mt][n][1];
            base[px0 + 8]        = acc[mt][n][2];
            base[1024 + px0 + 8] = acc[mt][n][3];
        }
    }
}

// ---------------------------------------------------------------------------
// K2: E[S^2] from noisy psum + EXACT mean from g_U and weight signs.
// ---------------------------------------------------------------------------
__global__ void k_stats(const float* __restrict__ gamma,
                        const float* __restrict__ beta,
                        const float* __restrict__ w) {
    const int ch = blockIdx.x;     // 1024
    const int t  = threadIdx.x;    // 256
    const int g  = ch >> 8;
    const int co = ch & 255;
    __shared__ float  rq[256];
    __shared__ double rm[64];

    float q = 0.0f;
    for (int i = t; i < 32768; i += 256) {
        const int bb = i >> 10;
        const int px = i & 1023;
        const float v = g_psum[((size_t)(bb * 1024 + ch)) * 1024 + px];
        q += v * v;
    }
    rq[t] = q;

    if (t < 64) {
        const int ciglob = g * 64 + t;
        const float* wc = w + (size_t)co * 2304 + (size_t)ciglob * 9;
        double m = 0.0;
#pragma unroll
        for (int tap = 0; tap < 9; ++tap) {
            const double u = g_U[ciglob * 9 + tap];
            m += (wc[tap] >= 0.0f) ? u : -u;
        }
        rm[t] = m;
    }
    __syncthreads();
    for (int off = 128; off; off >>= 1) {
        if (t < off) rq[t] += rq[t + off];
        __syncthreads();
    }
    if (t == 0) {
        double msum = 0.0;
        for (int i = 0; i < 64; ++i) msum += rm[i];
        const double mean = msum * (1.0 / 32768.0);
        const double var  = (double)rq[0] * (1.0 / 32768.0) - mean * mean;
        const double a    = (double)g_alpha[co];
        const double inv  = (double)gamma[ch] / sqrt(a * a * var + 1e-5);
        const double sc   = a * inv;
        g_scale[ch] = (float)sc;
        g_bias[ch]  = (float)((double)beta[ch] - mean * sc);
    }
}

// ---------------------------------------------------------------------------
// K3: threshold + merge + qrelu LUT; flag near-threshold pixels.
// ---------------------------------------------------------------------------
__global__ void k_out(float* __restrict__ out) {
    const int idx = blockIdx.x * 256 + threadIdx.x;
    const int b    = idx >> 16;
    const int qb   = idx & 65535;
    const int co   = qb >> 8;
    const int pix4 = qb & 255;

    const float4* pb = reinterpret_cast<const float4*>(g_psum);
    int c0 = 0, c1 = 0, c2 = 0, c3 = 0;
    bool f0 = false, f1 = false, f2 = false, f3 = false;
#pragma unroll
    for (int g = 0; g < 4; g++) {
        const int chan = g * 256 + co;
        const float4 p = pb[(size_t)(b * 1024 + chan) * 256 + pix4];
        const float sc = g_scale[chan];
        const float bi = g_bias[chan];
        const float band = fabsf(sc) * TAU;
        const float m0 = p.x * sc + bi;
        const float m1 = p.y * sc + bi;
        const float m2 = p.z * sc + bi;
        const float m3 = p.w * sc + bi;
        c0 += (m0 >= 0.0f); f0 |= (fabsf(m0) < band);
        c1 += (m1 >= 0.0f); f1 |= (fabsf(m1) < band);
        c2 += (m2 >= 0.0f); f2 |= (fabsf(m2) < band);
        c3 += (m3 >= 0.0f); f3 |= (fabsf(m3) < band);
    }
    const float Q3 = (8.0f / 15.0f) * 4.0f;
    float4 o;
    o.x = (c0 == 4) ? 4.0f : ((c0 == 3) ? Q3 : 0.0f);
    o.y = (c1 == 4) ? 4.0f : ((c1 == 3) ? Q3 : 0.0f);
    o.z = (c2 == 4) ? 4.0f : ((c2 == 3) ? Q3 : 0.0f);
    o.w = (c3 == 4) ? 4.0f : ((c3 == 3) ? Q3 : 0.0f);
    reinterpret_cast<float4*>(out)[idx] = o;

    if (f0 | f1 | f2 | f3) {
        const int base = (b << 18) | (co << 10) | (pix4 << 2);
#pragma unroll
        for (int comp = 0; comp < 4; ++comp) {
            const bool f = (comp == 0) ? f0 : (comp == 1) ? f1 : (comp == 2) ? f2 : f3;
            if (f) {
                const int slot = atomicAdd(&g_cnt, 1);
                if (slot < CAP) g_list[slot] = base | comp;
            }
        }
    }
}

// ---------------------------------------------------------------------------
// K4: warp-per-item exact rescue from g_xt (coalesced over ci). Idempotent.
// Lanes cover 2 channels each within the flagged group; double butterfly
// reduce; lane 0 writes.
// ---------------------------------------------------------------------------
__global__ void k_fix(const float* __restrict__ w, float* __restrict__ out) {
    const int n = (g_cnt < CAP) ? g_cnt : CAP;
    const int lane = threadIdx.x & 31;
    const int nwarp = (gridDim.x * blockDim.x) >> 5;
    const int wg = (blockIdx.x * blockDim.x + threadIdx.x) >> 5;

    for (int i = wg; i < n; i += nwarp) {
        const int item = g_list[i];
        const int b   = item >> 18;
        const int co  = (item >> 10) & 255;
        const int pix = item & 1023;
        const int h = pix >> 5, wp = pix & 31;
        int c = 0;
#pragma unroll 1
        for (int g = 0; g < 4; g++) {
            const int chan = g * 256 + co;
            const float sc = g_scale[chan];
            const float bi = g_bias[chan];
            const float S  = g_psum[((size_t)(b * 1024 + chan)) * 1024 + pix];
            const float m  = S * sc + bi;
            int bit;
            if (fabsf(m) < fabsf(sc) * TAU) {
                double s = 0.0;
#pragma unroll
                for (int half = 0; half < 2; ++half) {
                    const int cig = lane + 32 * half;         // 0..63 in group
                    const int ciG = g * 64 + cig;
                    const float* wc = w + (size_t)co * 2304 + (size_t)ciG * 9;
#pragma unroll
                    for (int kh = 0; kh < 3; kh++) {
                        const int hh = h + kh - 1;
                        if ((unsigned)hh >= 32u) continue;
#pragma unroll
                        for (int kw = 0; kw < 3; kw++) {
                            const int ww = wp + kw - 1;
                            if ((unsigned)ww >= 32u) continue;
                            const float xv =
                                g_xt[((size_t)((b * 32 + hh) * 32 + ww)) * 256 + ciG];
                            s += (wc[kh * 3 + kw] >= 0.0f) ? (double)xv
                                                           : -(double)xv;
                        }
                    }
                }
#pragma unroll
                for (int off = 16; off; off >>= 1)
                    s += __shfl_xor_sync(0xFFFFFFFFu, s, off);
                const double md = s * (double)sc + (double)bi;
                bit = (md >= 0.0);
            } else {
                bit = (m >= 0.0f);
            }
            c += bit;
        }
        if (lane == 0) {
            const float Q3 = (8.0f / 15.0f) * 4.0f;
            out[((size_t)(b * 256 + co)) * 1024 + pix] =
                (c == 4) ? 4.0f : ((c == 3) ? Q3 : 0.0f);
        }
    }
}

// ---------------------------------------------------------------------------
extern "C" void kernel_launch(void* const* d_in, const int* in_sizes, int n_in,
                              void* d_out, int out_size) {
    const float* x      = (const float*)d_in[0];
    const float* weight = (const float*)d_in[1];
    const float* gamma  = (const float*)d_in[2];
    const float* beta   = (const float*)d_in[3];
    float* out = (float*)d_out;

    cudaFuncSetAttribute(k_conv, cudaFuncAttributeMaxDynamicSharedMemorySize, SM_BYTES);

    k_prep<<<256, 256>>>(weight);
    k_usum<<<2304, 256>>>(x);
    k_xt<<<dim3(8, 32, 32), dim3(32, 8)>>>(x);
    k_conv<<<dim3(8, 4, 32), 512, SM_BYTES>>>(x);
    k_stats<<<1024, 256>>>(gamma, beta, weight);
    k_out<<<8192, 256>>>(out);
    k_fix<<<2048, 256>>>(weight, out);
}